// round 4
// baseline (speedup 1.0000x reference)
#include <cuda_runtime.h>
#include <cuda_bf16.h>
#include <cstdint>

#define N_TOK 8192
#define DMODEL 1024
#define NEXP 8

// Scratch (allocation-free rule: __device__ globals)
__device__ int g_inv[NEXP * N_TOK];   // inv[e][p] = token occupying slot p of expert e
__device__ int g_loads[NEXP];

// ---------------------------------------------------------------------------
// Kernel 1: per-expert mask + prefix scan -> inverse index + loads
// grid = NEXP blocks, 1024 threads. Each block owns one expert column but
// loads the FULL 8-gate row vectorized (coalesced float4 x2) and picks its bit.
// ---------------------------------------------------------------------------
__global__ __launch_bounds__(1024) void route_scan_kernel(
    const float* __restrict__ gates,   // [N_TOK, NEXP]
    float* __restrict__ loads_out,     // tail of d_out (may be null)
    int write_loads)
{
    const int e    = blockIdx.x;
    const int tid  = threadIdx.x;
    const int lane = tid & 31;
    const int wid  = tid >> 5;

    __shared__ int warp_sums[32];

    int offset = 0;  // running routed count for this expert

    #pragma unroll 1
    for (int base = 0; base < N_TOK; base += 1024) {
        const int t = base + tid;
        const float4* grow = reinterpret_cast<const float4*>(gates + (size_t)t * NEXP);
        const float4 g0 = __ldg(grow);
        const float4 g1 = __ldg(grow + 1);
        float gv[NEXP] = {g0.x, g0.y, g0.z, g0.w, g1.x, g1.y, g1.z, g1.w};

        int m;
        if (e == 0) {
            bool any = false;
            #pragma unroll
            for (int j = 0; j < NEXP; j++) any = any || (gv[j] > 0.0f);
            m = (gv[0] > 0.0f) || (!any);   // expert 0 absorbs residual tokens
        } else {
            m = (gv[e] > 0.0f) ? 1 : 0;
        }

        // warp inclusive scan
        int incl = m;
        #pragma unroll
        for (int d = 1; d < 32; d <<= 1) {
            int v = __shfl_up_sync(0xffffffffu, incl, d);
            if (lane >= d) incl += v;
        }
        if (lane == 31) warp_sums[wid] = incl;
        __syncthreads();

        if (wid == 0) {
            int v = warp_sums[lane];
            #pragma unroll
            for (int d = 1; d < 32; d <<= 1) {
                int u = __shfl_up_sync(0xffffffffu, v, d);
                if (lane >= d) v += u;
            }
            warp_sums[lane] = v;  // inclusive warp-total scan
        }
        __syncthreads();

        const int warp_off = (wid > 0) ? warp_sums[wid - 1] : 0;
        const int pos = offset + warp_off + incl - 1;  // exclusive position
        if (m) g_inv[e * N_TOK + pos] = t;

        offset += warp_sums[31];
        __syncthreads();  // warp_sums reused next iteration
    }

    if (tid == 0) {
        g_loads[e] = offset;
        if (write_loads) loads_out[e] = (float)offset;
    }
}

// ---------------------------------------------------------------------------
// Kernel 2: gather-write the full (E, N, D) output; every byte written once.
// grid = NEXP * N_TOK / 2 blocks, 256 threads; each block writes TWO D-rows
// (slots 2p and 2p+1) of expert e = bid & 7. Two independent float4
// load/store chains per thread -> MLP=2, fully coalesced 16B accesses.
// Expert-interleaved bid layout keeps concurrent gathers in nearby token
// rows -> L2 reuse of in_flow.
// ---------------------------------------------------------------------------
__global__ __launch_bounds__(256) void gather_write_kernel(
    const float* __restrict__ in_flow,  // [N_TOK, DMODEL]
    float* __restrict__ out)            // [NEXP, N_TOK, DMODEL]
{
    const int bid = blockIdx.x;
    const int e   = bid & (NEXP - 1);
    const int pp  = bid >> 3;          // slot pair index
    const int p0  = pp * 2;
    const int tid = threadIdx.x;

    const int load = g_loads[e];
    const float4 z = make_float4(0.0f, 0.0f, 0.0f, 0.0f);

    float4 v0 = z, v1 = z;
    if (p0 < load) {
        const int t0 = g_inv[e * N_TOK + p0];
        v0 = __ldg(reinterpret_cast<const float4*>(in_flow + (size_t)t0 * DMODEL) + tid);
    }
    if (p0 + 1 < load) {
        const int t1 = g_inv[e * N_TOK + p0 + 1];
        v1 = __ldg(reinterpret_cast<const float4*>(in_flow + (size_t)t1 * DMODEL) + tid);
    }

    float4* orow = reinterpret_cast<float4*>(out + ((size_t)e * N_TOK + p0) * DMODEL);
    orow[tid] = v0;
    orow[tid + DMODEL / 4] = v1;
}

// ---------------------------------------------------------------------------
extern "C" void kernel_launch(void* const* d_in, const int* in_sizes, int n_in,
                              void* d_out, int out_size)
{
    const float* in_flow = (const float*)d_in[0];   // [8192, 1024] f32
    const float* gates   = (const float*)d_in[1];   // [8192, 8]    f32
    float* out = (float*)d_out;

    const long long flows_elems = (long long)NEXP * N_TOK * DMODEL;
    const int write_loads = ((long long)out_size >= flows_elems + NEXP) ? 1 : 0;
    float* loads_out = out + flows_elems;

    route_scan_kernel<<<NEXP, 1024>>>(gates, loads_out, write_loads);
    gather_write_kernel<<<NEXP * N_TOK / 2, 256>>>(in_flow, out);
}

// round 6
// speedup vs baseline: 1.1036x; 1.1036x over previous
#include <cuda_runtime.h>
#include <cuda_bf16.h>
#include <cstdint>

#define N_TOK 8192
#define DMODEL 1024
#define NEXP 8
#define MASK_BLOCKS 32          // 32 blocks x 256 threads = 8192 tokens
#define ROWS_PER_BLOCK 4

// Scratch (allocation-free rule: __device__ globals)
__device__ int          g_inv[NEXP * N_TOK];        // inv[e][p] = token at slot p of expert e
__device__ int          g_loads[NEXP];
__device__ unsigned int g_mask[N_TOK];              // 8-bit routing mask per token
__device__ int          g_blockcnt[MASK_BLOCKS * NEXP];
__device__ int          g_blockoff[MASK_BLOCKS * NEXP];

// ---------------------------------------------------------------------------
// Kernel A: compute per-token mask byte + per-(block,expert) counts.
// ---------------------------------------------------------------------------
__global__ __launch_bounds__(256) void mask_count_kernel(const float* __restrict__ gates)
{
    const int tid  = threadIdx.x;
    const int lane = tid & 31;
    const int wid  = tid >> 5;
    const int t    = blockIdx.x * 256 + tid;

    const float4* grow = reinterpret_cast<const float4*>(gates + (size_t)t * NEXP);
    const float4 g0 = __ldg(grow);
    const float4 g1 = __ldg(grow + 1);
    const float gv[NEXP] = {g0.x, g0.y, g0.z, g0.w, g1.x, g1.y, g1.z, g1.w};

    unsigned int m = 0;
    #pragma unroll
    for (int e = 0; e < NEXP; e++) m |= (gv[e] > 0.0f) ? (1u << e) : 0u;
    if (m == 0u) m = 1u;                 // residual -> expert 0
    g_mask[t] = m;

    __shared__ int wcnt[8][NEXP];        // [warp][expert]
    #pragma unroll
    for (int e = 0; e < NEXP; e++) {
        const unsigned int b = __ballot_sync(0xffffffffu, (m >> e) & 1u);
        if (lane == 0) wcnt[wid][e] = __popc(b);
    }
    __syncthreads();

    if (tid < NEXP) {
        int s = 0;
        #pragma unroll
        for (int w = 0; w < 8; w++) s += wcnt[w][tid];
        g_blockcnt[blockIdx.x * NEXP + tid] = s;
    }
}

// ---------------------------------------------------------------------------
// Kernel B: scan the 32 per-block counts per expert -> block offsets + loads.
// ---------------------------------------------------------------------------
__global__ __launch_bounds__(32) void scan_offsets_kernel(
    float* __restrict__ loads_out, int write_loads)
{
    const int e = threadIdx.x;
    if (e < NEXP) {
        int run = 0;
        #pragma unroll
        for (int b = 0; b < MASK_BLOCKS; b++) {
            const int c = g_blockcnt[b * NEXP + e];
            g_blockoff[b * NEXP + e] = run;
            run += c;
        }
        g_loads[e] = run;
        if (write_loads) loads_out[e] = (float)run;
    }
}

// ---------------------------------------------------------------------------
// Kernel C: emit inverse index. Intra-block position via ballot prefix +
// per-warp shared-memory exclusive scan; global position via g_blockoff.
// ---------------------------------------------------------------------------
__global__ __launch_bounds__(256) void emit_inv_kernel()
{
    const int tid  = threadIdx.x;
    const int lane = tid & 31;
    const int wid  = tid >> 5;
    const int t    = blockIdx.x * 256 + tid;

    const unsigned int m = g_mask[t];
    const unsigned int lt = (1u << lane) - 1u;

    unsigned int bal[NEXP];
    __shared__ int wcnt[8][NEXP];
    #pragma unroll
    for (int e = 0; e < NEXP; e++) {
        bal[e] = __ballot_sync(0xffffffffu, (m >> e) & 1u);
        if (lane == 0) wcnt[wid][e] = __popc(bal[e]);
    }
    __syncthreads();

    if (tid < NEXP) {                    // exclusive scan over 8 warps, expert=tid
        int run = 0;
        #pragma unroll
        for (int w = 0; w < 8; w++) {
            const int c = wcnt[w][tid];
            wcnt[w][tid] = run;
            run += c;
        }
    }
    __syncthreads();

    const int boff_base = blockIdx.x * NEXP;
    #pragma unroll
    for (int e = 0; e < NEXP; e++) {
        if ((m >> e) & 1u) {
            const int pos = g_blockoff[boff_base + e] + wcnt[wid][e] + __popc(bal[e] & lt);
            g_inv[e * N_TOK + pos] = t;
        }
    }
}

// ---------------------------------------------------------------------------
// Kernel D: gather-write the full (E, N, D) output; every byte written once.
// 4 rows per block -> 4 independent LDG.128/STG.128 chains per thread (MLP=4).
// Streaming stores (__stcs) keep the 256MB output from evicting in_flow in L2.
// Expert-interleaved bid layout -> concurrent gathers hit nearby token rows.
// ---------------------------------------------------------------------------
__global__ __launch_bounds__(256) void gather_write_kernel(
    const float* __restrict__ in_flow,  // [N_TOK, DMODEL]
    float* __restrict__ out)            // [NEXP, N_TOK, DMODEL]
{
    const int bid = blockIdx.x;
    const int e   = bid & (NEXP - 1);
    const int p0  = (bid >> 3) * ROWS_PER_BLOCK;
    const int tid = threadIdx.x;

    const int load = g_loads[e];
    const float4 z = make_float4(0.0f, 0.0f, 0.0f, 0.0f);

    float4 v[ROWS_PER_BLOCK];
    #pragma unroll
    for (int r = 0; r < ROWS_PER_BLOCK; r++) {
        v[r] = z;
        if (p0 + r < load) {
            const int t = g_inv[e * N_TOK + p0 + r];
            v[r] = __ldg(reinterpret_cast<const float4*>(in_flow + (size_t)t * DMODEL) + tid);
        }
    }

    float4* orow = reinterpret_cast<float4*>(out + ((size_t)e * N_TOK + p0) * DMODEL);
    #pragma unroll
    for (int r = 0; r < ROWS_PER_BLOCK; r++)
        __stcs(orow + r * (DMODEL / 4) + tid, v[r]);
}

// ---------------------------------------------------------------------------
extern "C" void kernel_launch(void* const* d_in, const int* in_sizes, int n_in,
                              void* d_out, int out_size)
{
    const float* in_flow = (const float*)d_in[0];   // [8192, 1024] f32
    const float* gates   = (const float*)d_in[1];   // [8192, 8]    f32
    float* out = (float*)d_out;

    const long long flows_elems = (long long)NEXP * N_TOK * DMODEL;
    const int write_loads = ((long long)out_size >= flows_elems + NEXP) ? 1 : 0;
    float* loads_out = out + flows_elems;

    mask_count_kernel<<<MASK_BLOCKS, 256>>>(gates);
    scan_offsets_kernel<<<1, 32>>>(loads_out, write_loads);
    emit_inv_kernel<<<MASK_BLOCKS, 256>>>();
    gather_write_kernel<<<NEXP * N_TOK / ROWS_PER_BLOCK, 256>>>(in_flow, out);
}

// round 7
// speedup vs baseline: 1.1417x; 1.0345x over previous
#include <cuda_runtime.h>
#include <cuda_bf16.h>
#include <cstdint>

#define N_TOK 8192
#define DMODEL 1024
#define NEXP 8
#define MASK_BLOCKS 32          // 32 blocks x 256 threads = 8192 tokens
#define ROWS_PER_BLOCK 4

// Scratch (allocation-free rule: __device__ globals)
__device__ int          g_inv[NEXP * N_TOK];      // inv[e][p] = token at slot p of expert e
__device__ int          g_loads[NEXP];
__device__ int4         g_blockcnt4[MASK_BLOCKS * 2];  // 8 counts per block, 16B-aligned
__device__ volatile int g_flag[MASK_BLOCKS];           // publish flags (reset by gather kernel)

// ---------------------------------------------------------------------------
// Kernel 1 (fused routing): mask -> per-block counts -> cross-block
// publish/poll -> per-block prefix -> emit inverse index + loads.
// All 32 blocks are co-resident (32 << 148 SMs), so the poll cannot deadlock.
// ---------------------------------------------------------------------------
__global__ __launch_bounds__(256) void route_kernel(
    const float* __restrict__ gates,   // [N_TOK, NEXP]
    float* __restrict__ loads_out,     // tail of d_out
    int write_loads)
{
    const int b    = blockIdx.x;
    const int tid  = threadIdx.x;
    const int lane = tid & 31;
    const int wid  = tid >> 5;
    const int t    = b * 256 + tid;

    // --- mask byte (kept in registers; no gmem round-trip) ---
    const float4* grow = reinterpret_cast<const float4*>(gates + (size_t)t * NEXP);
    const float4 g0 = __ldg(grow);
    const float4 g1 = __ldg(grow + 1);
    const float gv[NEXP] = {g0.x, g0.y, g0.z, g0.w, g1.x, g1.y, g1.z, g1.w};

    unsigned int m = 0;
    #pragma unroll
    for (int e = 0; e < NEXP; e++) m |= (gv[e] > 0.0f) ? (1u << e) : 0u;
    if (m == 0u) m = 1u;               // residual -> expert 0

    // --- per-warp counts via ballot ---
    __shared__ int wcnt[8][NEXP];
    __shared__ int boff[NEXP];
    unsigned int bal[NEXP];
    #pragma unroll
    for (int e = 0; e < NEXP; e++) {
        bal[e] = __ballot_sync(0xffffffffu, (m >> e) & 1u);
        if (lane == 0) wcnt[wid][e] = __popc(bal[e]);
    }
    __syncthreads();

    // --- one thread publishes this block's 8 counts, then raises its flag ---
    if (tid == 0) {
        int c[NEXP];
        #pragma unroll
        for (int e = 0; e < NEXP; e++) {
            int s = 0;
            #pragma unroll
            for (int w = 0; w < 8; w++) s += wcnt[w][e];
            c[e] = s;
        }
        g_blockcnt4[b * 2 + 0] = make_int4(c[0], c[1], c[2], c[3]);
        g_blockcnt4[b * 2 + 1] = make_int4(c[4], c[5], c[6], c[7]);
        __threadfence();               // counts visible before flag
        g_flag[b] = 1;
    }

    // --- warp 0 polls all 32 flags (each lane watches one) ---
    if (wid == 0) {
        while (g_flag[lane] == 0) { }
        __threadfence();               // no count-read hoisted above the poll
    }
    __syncthreads();

    // --- per-expert: warp-exclusive scan + this block's global offset ---
    if (tid < NEXP) {
        int run = 0;
        #pragma unroll
        for (int w = 0; w < 8; w++) {  // wcnt -> exclusive warp offsets
            const int c = wcnt[w][tid];
            wcnt[w][tid] = run;
            run += c;
        }
        const int* cnts = reinterpret_cast<const int*>(g_blockcnt4);
        int off = 0, total = 0;
        #pragma unroll
        for (int b2 = 0; b2 < MASK_BLOCKS; b2++) {
            const int c = cnts[b2 * NEXP + tid];
            if (b2 < b) off += c;
            total += c;
        }
        boff[tid] = off;
        if (b == 0) {
            g_loads[tid] = total;
            if (write_loads) loads_out[tid] = (float)total;
        }
    }
    __syncthreads();

    // --- emit inverse index ---
    const unsigned int lt = (1u << lane) - 1u;
    #pragma unroll
    for (int e = 0; e < NEXP; e++) {
        if ((m >> e) & 1u) {
            const int pos = boff[e] + wcnt[wid][e] + __popc(bal[e] & lt);
            g_inv[e * N_TOK + pos] = t;
        }
    }
}

// ---------------------------------------------------------------------------
// Kernel 2: gather-write the full (E, N, D) output; every byte written once.
// 4 rows/block, 4 independent LDG.128/STG.128 chains (MLP=4), streaming
// stores keep the 256MB output from evicting in_flow in L2.
// Block 0 also resets the routing flags for the next graph replay.
// ---------------------------------------------------------------------------
__global__ __launch_bounds__(256) void gather_write_kernel(
    const float* __restrict__ in_flow,  // [N_TOK, DMODEL]
    float* __restrict__ out)            // [NEXP, N_TOK, DMODEL]
{
    const int bid = blockIdx.x;
    const int e   = bid & (NEXP - 1);
    const int p0  = (bid >> 3) * ROWS_PER_BLOCK;
    const int tid = threadIdx.x;

    if (bid == 0 && tid < MASK_BLOCKS) g_flag[tid] = 0;   // reset for next replay

    const int load = g_loads[e];
    const float4 z = make_float4(0.0f, 0.0f, 0.0f, 0.0f);

    float4 v[ROWS_PER_BLOCK];
    #pragma unroll
    for (int r = 0; r < ROWS_PER_BLOCK; r++) {
        v[r] = z;
        if (p0 + r < load) {
            const int t = g_inv[e * N_TOK + p0 + r];
            v[r] = __ldg(reinterpret_cast<const float4*>(in_flow + (size_t)t * DMODEL) + tid);
        }
    }

    float4* orow = reinterpret_cast<float4*>(out + ((size_t)e * N_TOK + p0) * DMODEL);
    #pragma unroll
    for (int r = 0; r < ROWS_PER_BLOCK; r++)
        __stcs(orow + r * (DMODEL / 4) + tid, v[r]);
}

// ---------------------------------------------------------------------------
extern "C" void kernel_launch(void* const* d_in, const int* in_sizes, int n_in,
                              void* d_out, int out_size)
{
    const float* in_flow = (const float*)d_in[0];   // [8192, 1024] f32
    const float* gates   = (const float*)d_in[1];   // [8192, 8]    f32
    float* out = (float*)d_out;

    const long long flows_elems = (long long)NEXP * N_TOK * DMODEL;
    const int write_loads = ((long long)out_size >= flows_elems + NEXP) ? 1 : 0;
    float* loads_out = out + flows_elems;

    route_kernel<<<MASK_BLOCKS, 256>>>(gates, loads_out, write_loads);
    gather_write_kernel<<<NEXP * N_TOK / ROWS_PER_BLOCK, 256>>>(in_flow, out);
}